// round 12
// baseline (speedup 1.0000x reference)
#include <cuda_runtime.h>
#include <cstdint>

static constexpr int Bn = 8;
static constexpr int NA = 262144;
static constexpr int Mg = 100;
static constexpr int Cc = 7;
static constexpr int GW = 128;            // cell = 8.0 units over [0,1024)
static constexpr int NCELLS = GW * GW;    // 16384
static constexpr int NWORDS = NA / 32;    // 8192 words per image
static constexpr int CAP = 64;            // bucket capacity (Poisson(16), overflow ~1e-18)

static constexpr int NB  = 148;           // 1 block/SM -> co-resident
static constexpr int NT  = 1024;
static constexpr int GEO = 48;            // geometry blocks (0..47)
static constexpr int ASG = 25;            // assign blocks (0..24), 32 warps each = 800
static constexpr int GEO_THR = GEO * NT;  // 49152

static constexpr int F4_IMG  = NA * Cc / 4;    // 458752 f4 per image
static constexpr int CHUNK_B = 32768;          // 32KB chunk = 2048 f4
static constexpr int CH_IMG  = 224;            // chunks per image
static constexpr int NSLOT = 4;
static constexpr int RING_BYTES = NSLOT * CHUNK_B;   // 131072
static constexpr int SMEM_DYN   = RING_BYTES + 64;   // ring + 4 mbarriers

// ---- device scratch (static zero-init; kernel re-zeroes at end of each call) ----
__device__ int                g_cellCnt[NCELLS];
__device__ float4             g_item[NCELLS * CAP];   // (x, y, bits(idx), 0)
__device__ unsigned int       g_nonneg[Bn * NWORDS];
__device__ unsigned long long g_best[Bn * Mg];
__device__ double             g_bceSum[Bn];
__device__ int                g_cnt[Bn];
__device__ int                g_cur[Bn];              // per-image chunk cursors
__device__ unsigned int          g_barCnt = 0;
__device__ volatile unsigned int g_barGen = 0;
__device__ unsigned int          g_geoCnt = 0;
__device__ volatile unsigned int g_geoGen = 0;

// ---- software barriers (all NB blocks co-resident) ----
__device__ __forceinline__ void gridBarrier() {
    __syncthreads();
    if (threadIdx.x == 0) {
        unsigned gen = g_barGen;
        __threadfence();
        if (atomicAdd(&g_barCnt, 1u) == NB - 1) {
            g_barCnt = 0;
            __threadfence();
            g_barGen = gen + 1;
        } else {
            while (g_barGen == gen) __nanosleep(64);
        }
        __threadfence();
    }
    __syncthreads();
}

__device__ __forceinline__ void geoBarrier() {       // blocks 0..GEO-1 only
    __syncthreads();
    if (threadIdx.x == 0) {
        unsigned gen = g_geoGen;
        __threadfence();
        if (atomicAdd(&g_geoCnt, 1u) == GEO - 1) {
            g_geoCnt = 0;
            __threadfence();
            g_geoGen = gen + 1;
        } else {
            while (g_geoGen == gen) __nanosleep(64);
        }
        __threadfence();
    }
    __syncthreads();
}

__device__ __forceinline__ int cellOf(float x) {
    int c = (int)(x * 0.125f);
    return min(GW - 1, max(0, c));
}

// ---- batched softplus: sum over 8 elems with ONE lg2 (verified exact-enough; rel_err 0.0) ----
__device__ __forceinline__ float ex2f(float x) {
    float r; asm("ex2.approx.f32 %0, %1;" : "=f"(r) : "f"(x)); return r;
}
__device__ __forceinline__ float lg2f(float x) {
    float r; asm("lg2.approx.f32 %0, %1;" : "=f"(r) : "f"(x)); return r;
}
__device__ __forceinline__ float sp8(float4 a, float4 b) {
    const float NL2E = -1.4426950408889634f;
    float w0 = 1.0f + ex2f(fabsf(a.x) * NL2E);
    float w1 = 1.0f + ex2f(fabsf(a.y) * NL2E);
    float w2 = 1.0f + ex2f(fabsf(a.z) * NL2E);
    float w3 = 1.0f + ex2f(fabsf(a.w) * NL2E);
    float w4 = 1.0f + ex2f(fabsf(b.x) * NL2E);
    float w5 = 1.0f + ex2f(fabsf(b.y) * NL2E);
    float w6 = 1.0f + ex2f(fabsf(b.z) * NL2E);
    float w7 = 1.0f + ex2f(fabsf(b.w) * NL2E);
    float p = ((w0 * w1) * (w2 * w3)) * ((w4 * w5) * (w6 * w7));   // in (1, 256]
    float m = (fmaxf(a.x, 0.f) + fmaxf(a.y, 0.f)) + (fmaxf(a.z, 0.f) + fmaxf(a.w, 0.f))
            + (fmaxf(b.x, 0.f) + fmaxf(b.y, 0.f)) + (fmaxf(b.z, 0.f) + fmaxf(b.w, 0.f));
    return fmaf(0.6931471805599453f, lg2f(p), m);
}

// ---- mbarrier / bulk-copy helpers ----
__device__ __forceinline__ void mbarInit(uint32_t addr, uint32_t count) {
    asm volatile("mbarrier.init.shared.b64 [%0], %1;" :: "r"(addr), "r"(count) : "memory");
}
__device__ __forceinline__ void mbarExpectTx(uint32_t addr, uint32_t bytes) {
    asm volatile("mbarrier.arrive.expect_tx.shared.b64 _, [%0], %1;"
                 :: "r"(addr), "r"(bytes) : "memory");
}
__device__ __forceinline__ void bulkCopyG2S(uint32_t dstSmem, const void* srcGmem,
                                            uint32_t bytes, uint32_t mbar) {
    asm volatile("cp.async.bulk.shared::cta.global.mbarrier::complete_tx::bytes "
                 "[%0], [%1], %2, [%3];"
                 :: "r"(dstSmem), "l"(srcGmem), "r"(bytes), "r"(mbar) : "memory");
}
__device__ __forceinline__ void mbarWait(uint32_t addr, uint32_t parity) {
    asm volatile(
        "{\n\t.reg .pred P1;\n"
        "WAIT_%=:\n\t"
        "mbarrier.try_wait.parity.acquire.cta.shared::cta.b64 P1, [%0], %1, 0x989680;\n\t"
        "@P1 bra DONE_%=;\n\t"
        "bra WAIT_%=;\n"
        "DONE_%=:\n\t}"
        :: "r"(addr), "r"(parity) : "memory");
}

// ---- bce: per-image chunk stealing, 4-deep 32KB TMA ring, 1024 consumers ----
__device__ void bceSteal(const float4* __restrict__ cls4, int b, int t, char* ring) {
    __shared__ double shb[32];
    __shared__ int sNum;
    int img = b & 7;
    const char* src0 = (const char*)(cls4 + (size_t)img * F4_IMG);
    uint32_t ringA = (uint32_t)__cvta_generic_to_shared(ring);
    uint32_t mbar0 = ringA + RING_BYTES;

    if (t == 0) {
        #pragma unroll
        for (int k = 0; k < NSLOT; k++) mbarInit(mbar0 + k * 8, 1);
        asm volatile("fence.proxy.async.shared::cta;" ::: "memory");
        int n = 0;
        #pragma unroll
        for (int k = 0; k < NSLOT; k++) {
            int c = atomicAdd(&g_cur[img], 1);
            if (c < CH_IMG) {
                mbarExpectTx(mbar0 + k * 8, CHUNK_B);
                bulkCopyG2S(ringA + k * CHUNK_B, src0 + (size_t)c * CHUNK_B,
                            CHUNK_B, mbar0 + k * 8);
                n++;
            }
        }
        sNum = n;
    }

    double acc = 0.0;
    int k = 0;
    for (;;) {
        __syncthreads();                  // orders t0's sNum update before read
        if (k >= sNum) break;             // uniform
        int slot = k & (NSLOT - 1);
        mbarWait(mbar0 + slot * 8, (k >> 2) & 1u);
        const float4* sl = (const float4*)(ring + slot * CHUNK_B);
        float4 a  = sl[t];
        float4 b2 = sl[NT + t];
        acc += (double)sp8(a, b2);
        __syncthreads();                  // slot fully consumed
        if (t == 0) {
            int c = atomicAdd(&g_cur[img], 1);
            if (c < CH_IMG) {
                mbarExpectTx(mbar0 + slot * 8, CHUNK_B);
                bulkCopyG2S(ringA + slot * CHUNK_B, src0 + (size_t)c * CHUNK_B,
                            CHUNK_B, mbar0 + slot * 8);
                sNum = sNum + 1;
            }
        }
        k++;
    }

    int w = t >> 5, lane = t & 31;
    #pragma unroll
    for (int o = 16; o; o >>= 1) acc += __shfl_down_sync(0xffffffffu, acc, o);
    if (lane == 0) shb[w] = acc;
    __syncthreads();
    if (t == 0) {
        double ssum = 0.0;
        #pragma unroll
        for (int j = 0; j < 32; j++) ssum += shb[j];
        atomicAdd(&g_bceSum[img], ssum);
    }
}

// d2 arithmetic replicates the reference bit-exactly (verified rel_err=0.0)
__device__ __forceinline__ void scanCell(
        int c, int lane, float gx, float gy, float gg,
        unsigned int* bm, int& newBits, unsigned long long& best) {
    int cnt = min(g_cellCnt[c], CAP);
    int base = c * CAP;
    for (int i = lane; i < cnt; i += 32) {
        float4 it = g_item[base + i];
        int n = __float_as_int(it.z);
        float aa  = __fadd_rn(__fmul_rn(it.x, it.x), __fmul_rn(it.y, it.y));
        float dot = __fmaf_rn(gy, it.y, __fmul_rn(gx, it.x));
        float d2  = __fsub_rn(__fadd_rn(gg, aa), __fadd_rn(dot, dot));
        if (d2 <= 9.0f) {
            unsigned bit = 1u << (n & 31);
            unsigned old = atomicOr(&bm[n >> 5], bit);
            if (!(old & bit)) newBits++;
        }
        float key = fmaxf(d2, 0.0f);
        unsigned long long pk =
            ((unsigned long long)__float_as_uint(key) << 32) | (unsigned)n;
        if (pk < best) best = pk;
    }
}

__device__ __forceinline__ unsigned long long warpMin(unsigned long long v) {
    #pragma unroll
    for (int off = 16; off; off >>= 1) {
        unsigned long long o = __shfl_xor_sync(0xffffffffu, v, off);
        if (o < v) v = o;
    }
    return v;
}

__device__ __forceinline__ void computeBox(int n, int b,
        const float* __restrict__ pred_reg, const float* __restrict__ anchors,
        const float* __restrict__ strides, float* box) {
    float s = strides[n];
    const float* r = &pred_reg[((size_t)b * NA + n) * 4];
    float ax = anchors[2 * n], ay = anchors[2 * n + 1];
    float cx = __fadd_rn(ax, __fmul_rn(r[0], s));
    float cy = __fadd_rn(ay, __fmul_rn(r[1], s));
    float w  = __fmul_rn(expf(r[2]), s);
    float h  = __fmul_rn(expf(r[3]), s);
    float w2 = __fmul_rn(w, 0.5f), h2 = __fmul_rn(h, 0.5f);
    box[0] = __fsub_rn(cx, w2);
    box[1] = __fsub_rn(cy, h2);
    box[2] = __fadd_rn(cx, w2);
    box[3] = __fadd_rn(cy, h2);
}

__device__ __forceinline__ float giouLoss(const float* p, const float* g) {
    const float EPS = 1e-7f;
    float ap = __fmul_rn(__fsub_rn(p[2], p[0]), __fsub_rn(p[3], p[1]));
    float ag = __fmul_rn(__fsub_rn(g[2], g[0]), __fsub_rn(g[3], g[1]));
    float ltx = fmaxf(p[0], g[0]), lty = fmaxf(p[1], g[1]);
    float rbx = fminf(p[2], g[2]), rby = fminf(p[3], g[3]);
    float wx = fmaxf(__fsub_rn(rbx, ltx), 0.f), wy = fmaxf(__fsub_rn(rby, lty), 0.f);
    float inter = __fmul_rn(wx, wy);
    float uni = __fsub_rn(__fadd_rn(ap, ag), inter);
    float iou = __fdiv_rn(inter, __fadd_rn(uni, EPS));
    float lcx = fminf(p[0], g[0]), lcy = fminf(p[1], g[1]);
    float rcx = fmaxf(p[2], g[2]), rcy = fmaxf(p[3], g[3]);
    float wcx = fmaxf(__fsub_rn(rcx, lcx), 0.f), wcy = fmaxf(__fsub_rn(rcy, lcy), 0.f);
    float ac = __fmul_rn(wcx, wcy);
    float giou = __fsub_rn(iou, __fdiv_rn(__fsub_rn(ac, uni), __fadd_rn(ac, EPS)));
    return __fsub_rn(1.0f, giou);
}

// ==================================================================
__global__ void __launch_bounds__(NT, 1) k_all(
        const float2* __restrict__ anchors2, const float* __restrict__ anchors,
        const float4* __restrict__ cls4,     const float* __restrict__ cls,
        const float* __restrict__ pred_reg,  const float* __restrict__ strides,
        const float* __restrict__ gt_boxes,  const int* __restrict__ gt_labels,
        float* __restrict__ out) {
    extern __shared__ __align__(16) char dynSmem[];
    const int b = blockIdx.x, t = threadIdx.x;

    if (b < GEO) {
        // ---- geometry: zero bitmap + scatter -> geo barrier -> assign ----
        int gid = b * NT + t;
        for (int n = gid; n < NA; n += GEO_THR) {
            float2 a = anchors2[n];
            int cell = cellOf(a.y) * GW + cellOf(a.x);
            int p = atomicAdd(&g_cellCnt[cell], 1);
            if (p < CAP) g_item[cell * CAP + p] = make_float4(a.x, a.y, __int_as_float(n), 0.f);
        }
        for (int i = gid; i < Bn * NWORDS; i += GEO_THR) g_nonneg[i] = 0u;
        geoBarrier();

        if (b < ASG) {
            int warpId = b * 32 + (t >> 5);       // 0..799, one warp per (img,gt)
            int lane = t & 31;
            int img = warpId / Mg, m = warpId % Mg;

            const float* g = &gt_boxes[(img * Mg + m) * 4];
            float gx = __fmul_rn(__fadd_rn(g[0], g[2]), 0.5f);
            float gy = __fmul_rn(__fadd_rn(g[1], g[3]), 0.5f);
            float gg = __fadd_rn(__fmul_rn(gx, gx), __fmul_rn(gy, gy));
            int cx0 = cellOf(gx), cy0 = cellOf(gy);
            unsigned int* bm = &g_nonneg[img * NWORDS];

            int newBits = 0;
            unsigned long long best = 0xFFFFFFFFFFFFFFFFULL;
            int ylo = max(cy0 - 1, 0), yhi = min(cy0 + 1, GW - 1);
            int xlo = max(cx0 - 1, 0), xhi = min(cx0 + 1, GW - 1);
            for (int cy = ylo; cy <= yhi; ++cy)
                for (int cx = xlo; cx <= xhi; ++cx)
                    scanCell(cy * GW + cx, lane, gx, gy, gg, bm, newBits, best);
            best = warpMin(best);

            float bk0 = __uint_as_float((unsigned)(best >> 32));
            if (!(bk0 < 62.0f)) {                 // fallback (essentially never)
                for (int k = 2; k < GW; ++k) {
                    int x0 = cx0 - k, x1 = cx0 + k, y0 = cy0 - k, y1 = cy0 + k;
                    int yl = max(y0, 0), yh = min(y1, GW - 1);
                    for (int cy = yl; cy <= yh; ++cy) {
                        bool edgeRow = (cy == y0 || cy == y1);
                        int xl = max(x0, 0), xh = min(x1, GW - 1);
                        for (int cx = xl; cx <= xh; ++cx) {
                            if (!edgeRow && cx != x0 && cx != x1) continue;
                            scanCell(cy * GW + cx, lane, gx, gy, gg, bm, newBits, best);
                        }
                    }
                    best = warpMin(best);
                    float bk = __uint_as_float((unsigned)(best >> 32));
                    float tt = 8.0f * (float)k;
                    if (bk < tt * tt - 2.0f) break;
                }
            }
            #pragma unroll
            for (int o = 16; o; o >>= 1) newBits += __shfl_down_sync(0xffffffffu, newBits, o);
            if (lane == 0) {
                g_best[warpId] = best;
                atomicAdd(&g_cnt[img], newBits);
            }
        }
        __syncthreads();
        bceSteal(cls4, b, t, dynSmem);   // join the bce stream (leftover chunks)
    } else {
        bceSteal(cls4, b, t, dynSmem);   // starts at cycle 0
    }
    gridBarrier();

    // ---- finalize: block 0; other blocks zero cellCnt for next call ----
    if (b != 0) {
        for (int i = (b - 1) * NT + t; i < NCELLS; i += (NB - 1) * NT)
            g_cellCnt[i] = 0;
        return;
    }

    // finalize arrays overlay the (now idle) smem ring of block 0
    int*   s_asg = (int*)(dynSmem);                   // 800*4  = 3200
    int*   s_cls = (int*)(dynSmem + 3200);            // 3200
    int*   s_srt = (int*)(dynSmem + 6400);            // 3200
    float* s_gtb = (float*)(dynSmem + 9600);          // 800*4*4 = 12800
    __shared__ double s_lc[Bn], s_lb[Bn];

    int w = t >> 5, lane = t & 31;
    if (w < 8) {
        int g = w;   // warp w -> image g

        for (int m = lane; m < Mg; m += 32) {
            s_asg[g * Mg + m] = (int)(unsigned)(g_best[g * Mg + m] & 0xFFFFFFFFULL);
            int l = gt_labels[g * Mg + m] - 1;
            s_cls[g * Mg + m] = min(max(l, 0), Cc - 1);
            #pragma unroll
            for (int j = 0; j < 4; j++)
                s_gtb[(g * Mg + m) * 4 + j] = gt_boxes[(g * Mg + m) * 4 + j];
        }
        __syncwarp();

        double corr = 0.0, posW = 0.0, ne = 0.0, eq = 0.0;
        int dis = 0;
        for (int m = lane; m < Mg; m += 32) {
            int a = s_asg[g * Mg + m], c = s_cls[g * Mg + m];
            bool dupA = false, dupAC = false;
            for (int u = 0; u < m; u++) {
                int au = s_asg[g * Mg + u];
                if (au == a) { dupA = true; if (s_cls[g * Mg + u] == c) dupAC = true; }
            }
            if (!dupA) {
                dis++;
                unsigned bit = (g_nonneg[g * NWORDS + (a >> 5)] >> (a & 31)) & 1u;
                posW += bit ? 0.1 : 1.0;
            }
            if (!dupAC)
                corr += (double)cls[((size_t)g * NA + a) * Cc + c];
            int rank = 0;
            for (int u = 0; u < Mg; u++) {
                int au = s_asg[g * Mg + u];
                if (au < a || (au == a && u < m)) rank++;
            }
            s_srt[g * Mg + rank] = a;
            float bx[4];
            computeBox(a, g, pred_reg, anchors, strides, bx);
            ne += (double)giouLoss(bx, &s_gtb[(g * Mg + m) * 4]);
        }
        __syncwarp();
        for (int m = lane; m < Mg; m += 32) {
            float bx[4];
            computeBox(s_srt[g * Mg + m], g, pred_reg, anchors, strides, bx);
            eq += (double)giouLoss(bx, &s_gtb[(g * Mg + m) * 4]);
        }

        #pragma unroll
        for (int o = 16; o; o >>= 1) {
            corr += __shfl_down_sync(0xffffffffu, corr, o);
            posW += __shfl_down_sync(0xffffffffu, posW, o);
            ne   += __shfl_down_sync(0xffffffffu, ne, o);
            eq   += __shfl_down_sync(0xffffffffu, eq, o);
            dis  += __shfl_down_sync(0xffffffffu, dis, o);
        }
        if (lane == 0) {
            int cnt = g_cnt[g];
            double sumSw = (double)(NA - cnt) + 0.1 * (double)cnt + posW;
            double meanSw = sumSw / (double)NA;
            double bceMean = (g_bceSum[g] - corr) / ((double)NA * (double)Cc);
            s_lc[g] = bceMean * meanSw;
            s_lb[g] = (dis == Mg ? eq : ne) * 0.01;
        }
    }
    __syncthreads();
    if (t == 0) {
        double lc = 0.0, lb = 0.0;
        #pragma unroll
        for (int i = 0; i < Bn; i++) { lc += s_lc[i]; lb += s_lb[i]; }
        out[0] = (float)(lc / (double)Bn + 2.0 * (lb / (double)Bn));
    }
    if (t < Bn) { g_cnt[t] = 0; g_bceSum[t] = 0.0; g_cur[t] = 0; }   // clean for next call
}

// ------------------------------------------------------------------
extern "C" void kernel_launch(void* const* d_in, const int* in_sizes, int n_in,
                              void* d_out, int out_size) {
    const float* pred_cls  = (const float*)d_in[0];
    const float* pred_reg  = (const float*)d_in[1];
    const float* anchors   = (const float*)d_in[2];
    const float* strides   = (const float*)d_in[3];
    const float* gt_boxes  = (const float*)d_in[4];
    const int*   gt_labels = (const int*)d_in[5];
    float* out = (float*)d_out;

    cudaFuncSetAttribute(k_all, cudaFuncAttributeMaxDynamicSharedMemorySize, SMEM_DYN);
    k_all<<<NB, NT, SMEM_DYN>>>((const float2*)anchors, anchors,
                                (const float4*)pred_cls, pred_cls,
                                pred_reg, strides, gt_boxes, gt_labels, out);
}

// round 13
// speedup vs baseline: 1.2908x; 1.2908x over previous
#include <cuda_runtime.h>

static constexpr int Bn = 8;
static constexpr int NA = 262144;
static constexpr int Mg = 100;
static constexpr int Cc = 7;
static constexpr int GW = 128;            // cell = 8.0 units over [0,1024)
static constexpr int NCELLS = GW * GW;    // 16384
static constexpr int NWORDS = NA / 32;    // 8192 words per image
static constexpr int CAP = 64;            // bucket capacity (Poisson(16), overflow ~1e-18)

static constexpr int NB = 296;            // 2 blocks/SM on 148 SMs -> co-resident
static constexpr int NT = 512;
static constexpr int NTHR = NB * NT;      // 151552

static constexpr int F4_IMG = NA * Cc / 4;     // 458752 float4 per image
static constexpr int CH_IMG = 112;             // chunks/image; chunk = 4096 f4 = 64KB
static constexpr int BCE_B0 = 50;              // first bce block
static constexpr int BCE_NBLK = 30;            // bce blocks per image (8*30 = 240)

// ---- device scratch (static zero-init; kernel leaves cnt arrays zeroed) ----
__device__ int                g_cellCnt[NCELLS];
__device__ int                g_itemIdx[NCELLS * CAP];   // anchor index only (4B)
__device__ unsigned int       g_nonneg[Bn * NWORDS];
__device__ unsigned long long g_best[Bn * Mg];
__device__ double             g_bceSum[Bn];
__device__ int                g_cnt[Bn];
__device__ unsigned int          g_barCnt = 0;
__device__ volatile unsigned int g_barGen = 0;

// ---- software grid barrier (all NB blocks co-resident) ----
__device__ __forceinline__ void gridBarrier() {
    __syncthreads();
    if (threadIdx.x == 0) {
        unsigned gen = g_barGen;
        __threadfence();
        if (atomicAdd(&g_barCnt, 1u) == NB - 1) {
            g_barCnt = 0;
            __threadfence();
            g_barGen = gen + 1;
        } else {
            while (g_barGen == gen) __nanosleep(64);
        }
        __threadfence();
    }
    __syncthreads();
}

__device__ __forceinline__ int cellOf(float x) {
    int c = (int)(x * 0.125f);
    return min(GW - 1, max(0, c));
}

// ---- batched softplus: sum over 8 elems with ONE lg2 (verified rel_err 0.0) ----
__device__ __forceinline__ float ex2f(float x) {
    float r; asm("ex2.approx.f32 %0, %1;" : "=f"(r) : "f"(x)); return r;
}
__device__ __forceinline__ float lg2f(float x) {
    float r; asm("lg2.approx.f32 %0, %1;" : "=f"(r) : "f"(x)); return r;
}
__device__ __forceinline__ float sp8(float4 a, float4 b) {
    const float NL2E = -1.4426950408889634f;
    float w0 = 1.0f + ex2f(fabsf(a.x) * NL2E);
    float w1 = 1.0f + ex2f(fabsf(a.y) * NL2E);
    float w2 = 1.0f + ex2f(fabsf(a.z) * NL2E);
    float w3 = 1.0f + ex2f(fabsf(a.w) * NL2E);
    float w4 = 1.0f + ex2f(fabsf(b.x) * NL2E);
    float w5 = 1.0f + ex2f(fabsf(b.y) * NL2E);
    float w6 = 1.0f + ex2f(fabsf(b.z) * NL2E);
    float w7 = 1.0f + ex2f(fabsf(b.w) * NL2E);
    float p = ((w0 * w1) * (w2 * w3)) * ((w4 * w5) * (w6 * w7));   // in (1, 256]
    float m = (fmaxf(a.x, 0.f) + fmaxf(a.y, 0.f)) + (fmaxf(a.z, 0.f) + fmaxf(a.w, 0.f))
            + (fmaxf(b.x, 0.f) + fmaxf(b.y, 0.f)) + (fmaxf(b.z, 0.f) + fmaxf(b.w, 0.f));
    return fmaf(0.6931471805599453f, lg2f(p), m);
}

// d2 arithmetic replicates the reference bit-exactly (verified rel_err=0.0).
// Items store only the index; coords re-gathered from anchors2 (same f32 values).
__device__ __forceinline__ void scanCell(
        int c, int lane, float gx, float gy, float gg,
        const float2* __restrict__ anchors2,
        unsigned int* bm, int& newBits, unsigned long long& best) {
    int cnt = min(g_cellCnt[c], CAP);
    int base = c * CAP;
    for (int i = lane; i < cnt; i += 32) {
        int n = g_itemIdx[base + i];
        float2 a = anchors2[n];
        float aa  = __fadd_rn(__fmul_rn(a.x, a.x), __fmul_rn(a.y, a.y));
        float dot = __fmaf_rn(gy, a.y, __fmul_rn(gx, a.x));
        float d2  = __fsub_rn(__fadd_rn(gg, aa), __fadd_rn(dot, dot));
        if (d2 <= 9.0f) {
            unsigned bit = 1u << (n & 31);
            unsigned old = atomicOr(&bm[n >> 5], bit);
            if (!(old & bit)) newBits++;
        }
        float key = fmaxf(d2, 0.0f);
        unsigned long long pk =
            ((unsigned long long)__float_as_uint(key) << 32) | (unsigned)n;
        if (pk < best) best = pk;
    }
}

__device__ __forceinline__ unsigned long long warpMin(unsigned long long v) {
    #pragma unroll
    for (int off = 16; off; off >>= 1) {
        unsigned long long o = __shfl_xor_sync(0xffffffffu, v, off);
        if (o < v) v = o;
    }
    return v;
}

__device__ __forceinline__ void computeBox(int n, int b,
        const float* __restrict__ pred_reg, const float* __restrict__ anchors,
        const float* __restrict__ strides, float* box) {
    float s = strides[n];
    const float* r = &pred_reg[((size_t)b * NA + n) * 4];
    float ax = anchors[2 * n], ay = anchors[2 * n + 1];
    float cx = __fadd_rn(ax, __fmul_rn(r[0], s));
    float cy = __fadd_rn(ay, __fmul_rn(r[1], s));
    float w  = __fmul_rn(expf(r[2]), s);
    float h  = __fmul_rn(expf(r[3]), s);
    float w2 = __fmul_rn(w, 0.5f), h2 = __fmul_rn(h, 0.5f);
    box[0] = __fsub_rn(cx, w2);
    box[1] = __fsub_rn(cy, h2);
    box[2] = __fadd_rn(cx, w2);
    box[3] = __fadd_rn(cy, h2);
}

__device__ __forceinline__ float giouLoss(const float* p, const float* g) {
    const float EPS = 1e-7f;
    float ap = __fmul_rn(__fsub_rn(p[2], p[0]), __fsub_rn(p[3], p[1]));
    float ag = __fmul_rn(__fsub_rn(g[2], g[0]), __fsub_rn(g[3], g[1]));
    float ltx = fmaxf(p[0], g[0]), lty = fmaxf(p[1], g[1]);
    float rbx = fminf(p[2], g[2]), rby = fminf(p[3], g[3]);
    float wx = fmaxf(__fsub_rn(rbx, ltx), 0.f), wy = fmaxf(__fsub_rn(rby, lty), 0.f);
    float inter = __fmul_rn(wx, wy);
    float uni = __fsub_rn(__fadd_rn(ap, ag), inter);
    float iou = __fdiv_rn(inter, __fadd_rn(uni, EPS));
    float lcx = fminf(p[0], g[0]), lcy = fminf(p[1], g[1]);
    float rcx = fmaxf(p[2], g[2]), rcy = fmaxf(p[3], g[3]);
    float wcx = fmaxf(__fsub_rn(rcx, lcx), 0.f), wcy = fmaxf(__fsub_rn(rcy, lcy), 0.f);
    float ac = __fmul_rn(wcx, wcy);
    float giou = __fsub_rn(iou, __fdiv_rn(__fsub_rn(ac, uni), __fadd_rn(ac, EPS)));
    return __fsub_rn(1.0f, giou);
}

// ==================================================================
__global__ void __launch_bounds__(NT, 2) k_all(
        const float2* __restrict__ anchors2, const float* __restrict__ anchors,
        const float4* __restrict__ cls4,     const float* __restrict__ cls,
        const float* __restrict__ pred_reg,  const float* __restrict__ strides,
        const float* __restrict__ gt_boxes,  const int* __restrict__ gt_labels,
        float* __restrict__ out) {
    const int b = blockIdx.x, t = threadIdx.x;
    const int gid = b * NT + t;

    // ---- phase A: scatter anchors (cellCnt zeroed by previous call / static init)
    //      + zero the non-neg bitmap for this call ----
    for (int n = gid; n < NA; n += NTHR) {
        float2 a = anchors2[n];
        int cell = cellOf(a.y) * GW + cellOf(a.x);
        int p = atomicAdd(&g_cellCnt[cell], 1);
        if (p < CAP) g_itemIdx[cell * CAP + p] = n;
    }
    for (int i = gid; i < Bn * NWORDS; i += NTHR) g_nonneg[i] = 0u;
    gridBarrier();

    // ---- phase B: assign (blocks 0..49)  ||  bce stream (blocks 50..289) ----
    if (b < BCE_B0) {
        // one warp per (img, gt)
        int warpId = b * 16 + (t >> 5);       // 0..799
        int lane = t & 31;
        int img = warpId / Mg, m = warpId % Mg;

        const float* g = &gt_boxes[(img * Mg + m) * 4];
        float gx = __fmul_rn(__fadd_rn(g[0], g[2]), 0.5f);
        float gy = __fmul_rn(__fadd_rn(g[1], g[3]), 0.5f);
        float gg = __fadd_rn(__fmul_rn(gx, gx), __fmul_rn(gy, gy));
        int cx0 = cellOf(gx), cy0 = cellOf(gy);
        unsigned int* bm = &g_nonneg[img * NWORDS];

        int newBits = 0;
        unsigned long long best = 0xFFFFFFFFFFFFFFFFULL;
        int ylo = max(cy0 - 1, 0), yhi = min(cy0 + 1, GW - 1);
        int xlo = max(cx0 - 1, 0), xhi = min(cx0 + 1, GW - 1);
        for (int cy = ylo; cy <= yhi; ++cy)
            for (int cx = xlo; cx <= xhi; ++cx)
                scanCell(cy * GW + cx, lane, gx, gy, gg, anchors2, bm, newBits, best);
        best = warpMin(best);

        float bk0 = __uint_as_float((unsigned)(best >> 32));
        if (!(bk0 < 62.0f)) {                 // fallback (essentially never)
            for (int k = 2; k < GW; ++k) {
                int x0 = cx0 - k, x1 = cx0 + k, y0 = cy0 - k, y1 = cy0 + k;
                int yl = max(y0, 0), yh = min(y1, GW - 1);
                for (int cy = yl; cy <= yh; ++cy) {
                    bool edgeRow = (cy == y0 || cy == y1);
                    int xl = max(x0, 0), xh = min(x1, GW - 1);
                    for (int cx = xl; cx <= xh; ++cx) {
                        if (!edgeRow && cx != x0 && cx != x1) continue;
                        scanCell(cy * GW + cx, lane, gx, gy, gg, anchors2, bm, newBits, best);
                    }
                }
                best = warpMin(best);
                float bk = __uint_as_float((unsigned)(best >> 32));
                float tt = 8.0f * (float)k;
                if (bk < tt * tt - 2.0f) break;
            }
        }
        #pragma unroll
        for (int o = 16; o; o >>= 1) newBits += __shfl_down_sync(0xffffffffu, newBits, o);
        if (lane == 0) {
            g_best[warpId] = best;
            atomicAdd(&g_cnt[img], newBits);
        }
    } else if (b < BCE_B0 + Bn * BCE_NBLK) {
        // bce: 240 blocks, 30 per image; chunks c = li, li+30, ... < 112
        __shared__ double shb[16];
        int idx = b - BCE_B0;
        int img = idx & 7, li = idx >> 3;     // li in [0, 30)
        const float4* base = cls4 + (size_t)img * F4_IMG;
        double acc = 0.0;
        for (int c = li; c < CH_IMG; c += BCE_NBLK) {
            const float4* p = base + c * 4096 + t;
            float4 v[8];
            #pragma unroll
            for (int j = 0; j < 8; j++)       // 8 coalesced LDG.128 in flight
                v[j] = p[j * 512];
            float a0 = (sp8(v[0], v[1]) + sp8(v[2], v[3]))
                     + (sp8(v[4], v[5]) + sp8(v[6], v[7]));
            acc += (double)a0;
        }
        #pragma unroll
        for (int o = 16; o; o >>= 1) acc += __shfl_down_sync(0xffffffffu, acc, o);
        if ((t & 31) == 0) shb[t >> 5] = acc;
        __syncthreads();
        if (t == 0) {
            double s = 0.0;
            #pragma unroll
            for (int j = 0; j < 16; j++) s += shb[j];
            atomicAdd(&g_bceSum[img], s);
        }
    }
    gridBarrier();

    // ---- phase C: block 0 finalizes; other blocks zero cellCnt for next call ----
    if (b != 0) {
        for (int i = (b - 1) * NT + t; i < NCELLS; i += (NB - 1) * NT)
            g_cellCnt[i] = 0;
        return;
    }

    __shared__ int   s_asg[Bn][Mg], s_cls[Bn][Mg], s_srt[Bn][Mg];
    __shared__ float s_gtb[Bn][Mg][4];
    __shared__ double s_lc[Bn], s_lb[Bn];

    int w = t >> 5, lane = t & 31;
    if (w < 8) {
        int g = w;   // warp w -> image g

        for (int m = lane; m < Mg; m += 32) {
            s_asg[g][m] = (int)(unsigned)(g_best[g * Mg + m] & 0xFFFFFFFFULL);
            int l = gt_labels[g * Mg + m] - 1;
            s_cls[g][m] = min(max(l, 0), Cc - 1);
            #pragma unroll
            for (int j = 0; j < 4; j++) s_gtb[g][m][j] = gt_boxes[(g * Mg + m) * 4 + j];
        }
        __syncwarp();

        double corr = 0.0, posW = 0.0, ne = 0.0, eq = 0.0;
        int dis = 0;
        for (int m = lane; m < Mg; m += 32) {
            int a = s_asg[g][m], c = s_cls[g][m];
            bool dupA = false, dupAC = false;
            for (int u = 0; u < m; u++) {
                int au = s_asg[g][u];
                if (au == a) { dupA = true; if (s_cls[g][u] == c) dupAC = true; }
            }
            if (!dupA) {
                dis++;
                unsigned bit = (g_nonneg[g * NWORDS + (a >> 5)] >> (a & 31)) & 1u;
                posW += bit ? 0.1 : 1.0;
            }
            if (!dupAC)
                corr += (double)cls[((size_t)g * NA + a) * Cc + c];
            int rank = 0;
            for (int u = 0; u < Mg; u++) {
                int au = s_asg[g][u];
                if (au < a || (au == a && u < m)) rank++;
            }
            s_srt[g][rank] = a;
            float bx[4];
            computeBox(a, g, pred_reg, anchors, strides, bx);
            ne += (double)giouLoss(bx, s_gtb[g][m]);
        }
        __syncwarp();
        for (int m = lane; m < Mg; m += 32) {
            float bx[4];
            computeBox(s_srt[g][m], g, pred_reg, anchors, strides, bx);
            eq += (double)giouLoss(bx, s_gtb[g][m]);
        }

        #pragma unroll
        for (int o = 16; o; o >>= 1) {
            corr += __shfl_down_sync(0xffffffffu, corr, o);
            posW += __shfl_down_sync(0xffffffffu, posW, o);
            ne   += __shfl_down_sync(0xffffffffu, ne, o);
            eq   += __shfl_down_sync(0xffffffffu, eq, o);
            dis  += __shfl_down_sync(0xffffffffu, dis, o);
        }
        if (lane == 0) {
            int cnt = g_cnt[g];
            double sumSw = (double)(NA - cnt) + 0.1 * (double)cnt + posW;
            double meanSw = sumSw / (double)NA;
            double bceMean = (g_bceSum[g] - corr) / ((double)NA * (double)Cc);
            s_lc[g] = bceMean * meanSw;
            s_lb[g] = (dis == Mg ? eq : ne) * 0.01;
        }
    }
    __syncthreads();
    if (t == 0) {
        double lc = 0.0, lb = 0.0;
        #pragma unroll
        for (int i = 0; i < Bn; i++) { lc += s_lc[i]; lb += s_lb[i]; }
        out[0] = (float)(lc / (double)Bn + 2.0 * (lb / (double)Bn));
    }
    if (t < Bn) { g_cnt[t] = 0; g_bceSum[t] = 0.0; }   // clean for next call
}

// ------------------------------------------------------------------
extern "C" void kernel_launch(void* const* d_in, const int* in_sizes, int n_in,
                              void* d_out, int out_size) {
    const float* pred_cls  = (const float*)d_in[0];
    const float* pred_reg  = (const float*)d_in[1];
    const float* anchors   = (const float*)d_in[2];
    const float* strides   = (const float*)d_in[3];
    const float* gt_boxes  = (const float*)d_in[4];
    const int*   gt_labels = (const int*)d_in[5];
    float* out = (float*)d_out;

    k_all<<<NB, NT>>>((const float2*)anchors, anchors,
                      (const float4*)pred_cls, pred_cls,
                      pred_reg, strides, gt_boxes, gt_labels, out);
}